// round 7
// baseline (speedup 1.0000x reference)
#include <cuda_runtime.h>
#include <math.h>

#define EPSF 1e-4f
typedef unsigned long long u64;

__device__ __forceinline__ u64 pack2(float x){
  u64 r; unsigned xi = __float_as_uint(x);
  asm("mov.b64 %0, {%1, %1};" : "=l"(r) : "r"(xi));
  return r;
}
__device__ __forceinline__ void fma2(u64 &acc, u64 a, u64 b){
  asm("fma.rn.f32x2 %0, %1, %2, %0;" : "+l"(acc) : "l"(a), "l"(b));
}
__device__ __forceinline__ float2 unpack2(u64 v){
  unsigned lo, hi;
  asm("mov.b64 {%0, %1}, %2;" : "=r"(lo), "=r"(hi) : "l"(v));
  return make_float2(__uint_as_float(lo), __uint_as_float(hi));
}
__device__ __forceinline__ float rsum32(float v){
  #pragma unroll
  for (int o=16;o;o>>=1) v += __shfl_xor_sync(0xffffffffu, v, o);
  return v;
}
__device__ __forceinline__ float rsum16(float v){
  #pragma unroll
  for (int o=8;o;o>>=1) v += __shfl_xor_sync(0xffffffffu, v, o);
  return v;
}
__device__ __forceinline__ float rmax16(float v){
  #pragma unroll
  for (int o=8;o;o>>=1) v = fmaxf(v, __shfl_xor_sync(0xffffffffu, v, o));
  return v;
}
__device__ __forceinline__ float sigm(float x){ return 1.f/(1.f+expf(-x)); }
__device__ __forceinline__ float splus(float x){ return fmaxf(x,0.f)+log1pf(expf(-fabsf(x))); }

__device__ __forceinline__ unsigned s2u(const void* p){
  return (unsigned)__cvta_generic_to_shared(p);
}
__device__ __forceinline__ void mbar_init(unsigned a, unsigned cnt){
  asm volatile("mbarrier.init.shared.b64 [%0], %1;" :: "r"(a), "r"(cnt) : "memory");
}
__device__ __forceinline__ void mbar_expect(unsigned a, unsigned tx){
  asm volatile("mbarrier.arrive.expect_tx.shared.b64 _, [%0], %1;" :: "r"(a), "r"(tx) : "memory");
}
__device__ __forceinline__ void bulk_g2s(unsigned dst, const void* src, unsigned bytes, unsigned mbar){
  asm volatile("cp.async.bulk.shared::cluster.global.mbarrier::complete_tx::bytes [%0], [%1], %2, [%3];"
    :: "r"(dst), "l"(src), "r"(bytes), "r"(mbar) : "memory");
}
__device__ __forceinline__ void mbar_wait(unsigned a, unsigned ph){
  unsigned done;
  asm volatile("{\n\t.reg .pred p;\n\t"
    "mbarrier.try_wait.parity.acquire.cta.shared::cta.b64 p, [%1], %2, 0x989680;\n\t"
    "selp.b32 %0,1,0,p;\n\t}"
    : "=r"(done) : "r"(a), "r"(ph) : "memory");
  if (!done){
    asm volatile("{\n\t.reg .pred p;\n"
      "WLOOP_%=:\n\t"
      "mbarrier.try_wait.parity.acquire.cta.shared::cta.b64 p, [%0], %1, 0x989680;\n\t"
      "@p bra WDONE_%=;\n\t"
      "bra WLOOP_%=;\n"
      "WDONE_%=:\n\t}"
      :: "r"(a), "r"(ph) : "memory");
  }
}

#define NST 5
#define NCHK 42
#define NTOT (NCHK*512)

struct Smem {
  float buf[NST][8192];     // 5 x 32KB ring
  u64   mfull[6];
  float sciT[260][4];
  float sh1T[128][4];
  float sct2[128][4];
  float sc[4][16][132];
  float smix[4][16][16];
  float satt[4][128];
  float sbuf[4][4][128];
  float ssp[4][16], smaM[4][16], sal[4][16], sgs[4][16];
  float ssq[4][16], sms[4][16], smm[4][16];
  float sred[4][4][3];
  float snv[4], srl[4], sval[4];
  int   sidx[4];
};

struct WPtrs {
  const float *w1, *w2, *att, *gw, *aw, *cw, *mw, *cc;
};

__device__ __forceinline__ void issue_one(int j, int st, unsigned bufB, unsigned mbB, const WPtrs& W){
  unsigned dst = bufB + (unsigned)st * 32768u;
  unsigned mb  = mbB + (unsigned)st * 8u;
  if (j < 5){
    unsigned by = (j == 4) ? 2048u : 32768u;
    mbar_expect(mb, by); bulk_g2s(dst, W.w1 + j*8192, by, mb);
  } else if (j < 7){
    mbar_expect(mb, 32768u); bulk_g2s(dst, W.w2 + (j-5)*8192, 32768u, mb);
  } else if (j < 9){
    mbar_expect(mb, 32768u); bulk_g2s(dst, W.att + (j-7)*8192, 32768u, mb);
  } else if (j == 9){
    mbar_expect(mb, 32768u);
    bulk_g2s(dst,          W.gw, 8192u, mb);
    bulk_g2s(dst +  8192u, W.aw, 8192u, mb);
    bulk_g2s(dst + 16384u, W.cw, 8192u, mb);
    bulk_g2s(dst + 24576u, W.mw, 8192u, mb);
  } else {
    mbar_expect(mb, 32768u); bulk_g2s(dst, W.cc + (j-10)*8192, 32768u, mb);
  }
}

__global__ void __launch_bounds__(512,1) cfrm_kernel(
   const int* __restrict__ tokens, const float* __restrict__ emb,
   const float* __restrict__ ln_g, const float* __restrict__ ln_b,
   const float* __restrict__ w1, const float* __restrict__ b1,
   const float* __restrict__ w2, const float* __restrict__ b2,
   const float* __restrict__ gate_w, const float* __restrict__ gate_b,
   const float* __restrict__ assign_w, const float* __restrict__ assign_b,
   const float* __restrict__ nov_w, const float* __restrict__ nov_b,
   const float* __restrict__ relax_w, const float* __restrict__ relax_b,
   const float* __restrict__ cc_w, const float* __restrict__ cc_b,
   const float* __restrict__ cs_w, const float* __restrict__ cs_b,
   const float* __restrict__ md_w, const float* __restrict__ md_b,
   const float* __restrict__ att_w, const float* __restrict__ att_b,
   const float* __restrict__ cw1, const float* __restrict__ cb1,
   const float* __restrict__ cw2, const float* __restrict__ cb2,
   float* __restrict__ out)
{
  extern __shared__ __align__(128) char smem_raw[];
  Smem* S = (Smem*)smem_raw;

  const int tid  = threadIdx.x;
  const int g    = tid >> 7;
  const int ht   = tid & 127;
  const int lane = tid & 31;
  const int wg   = (tid >> 5) & 3;
  const int b    = blockIdx.x * 4 + g;

  const int jjm = tid & 127;
  const int sl4 = tid >> 7;
  const int shd = tid >> 7;
  const int shc = (tid >> 3) & 15;
  const int shs = tid & 7;

  WPtrs WP{w1, w2, att_w, gate_w, assign_w, cs_w, md_w, cc_w};
  const unsigned mbB  = s2u(&S->mfull[0]);
  const unsigned bufB = s2u(&S->buf[0][0]);

  int stC = 0, phC = 0;
  int jI = 0, stI = 0, nI = 0;

  for (int i = tid; i < 4*16*132; i += 512) ((float*)S->sc)[i] = 0.f;
  if (tid < 64){ ((float*)S->ssp)[tid] = 1.f; ((float*)S->smaM)[tid] = 0.f; }
  if (tid == 0){
    #pragma unroll
    for (int s = 0; s < NST; s++) mbar_init(mbB + s*8u, 1);
    asm volatile("fence.proxy.async.shared::cta;" ::: "memory");
  }
  __syncthreads();

#define PRODUCE(k) do{ if (tid == 0){ \
    for (int z = 0; z < (k); z++){ \
      if (nI < NTOT) issue_one(jI, stI, bufB, mbB, WP); \
      nI++; if (++jI == NCHK) jI = 0; if (++stI == NST) stI = 0; } } }while(0)
#define WAITC() mbar_wait(mbB + (unsigned)stC*8u, phC)
#define ADVC()  do{ if (++stC == NST){ stC = 0; phC ^= 1; } }while(0)

  PRODUCE(5);

  for (int t = 0; t < 512; t++){
    const int tok = tokens[b*512 + t];
    const float valid = (tok != 0) ? 1.f : 0.f;
    if (ht == 0) S->sval[g] = valid;
    const float e = emb[tok*128 + ht];
    {
      float ps = rsum32(e);
      float pq = rsum32(e*e);
      if (lane == 0){ S->sred[g][wg][0] = ps; S->sred[g][wg][1] = pq; }
    }
    if (ht < 32){
      const bool ok = lane < 16;
      float sp = ok ? S->ssp[g][lane] : 0.f;
      float m  = ok ? S->smaM[g][lane] : 0.f;
      float score = ok ? m + logf(1.f/(sp+EPSF)+EPSF) : -3.4e38f;
      float mx = rmax16(score);
      float ex = ok ? expf(score - mx) : 0.f;
      float sm = rsum16(ex);
      float a  = ex / sm;
      if (ok) S->sal[g][lane] = a;
      float u   = rsum16(ok ? a*sp : 0.f);
      float ent = rsum16(ok ? -a*logf(fmaxf(a,1e-8f)) : 0.f);
      float mm2 = rmax16(ok ? m : -3.4e38f);
      float en  = mm2 + logf(rsum16(ok ? expf(m - mm2) : 0.f));
      if (lane == 0){ S->sciT[256][g] = u; S->sciT[258][g] = en; S->sciT[259][g] = ent; }
    }
    __syncthreads(); // S1
    {
      float mu = (S->sred[g][0][0]+S->sred[g][1][0]+S->sred[g][2][0]+S->sred[g][3][0]) * (1.f/128.f);
      float mq = (S->sred[g][0][1]+S->sred[g][1][1]+S->sred[g][2][1]+S->sred[g][3][1]) * (1.f/128.f);
      float var = mq - mu*mu;
      float te = (e - mu) * rsqrtf(var + 1e-5f) * ln_g[ht] + ln_b[ht];
      S->sciT[ht][g] = te;
      float core = 0.f;
      #pragma unroll
      for (int c = 0; c < 16; c++) core += S->sal[g][c] * S->sc[g][c][ht];
      S->sciT[128+ht][g] = core;
      float dv = 0.f;
      #pragma unroll
      for (int c = 0; c < 16; c++){ float dd = S->sc[g][c][ht] - core; dv += S->sal[g][c]*dd*dd; }
      dv = rsum32(dv);
      if (lane == 0) S->sred[g][wg][2] = dv;
    }
    __syncthreads(); // S2
    if (ht == 0)
      S->sciT[257][g] = (S->sred[g][0][2]+S->sred[g][1][2]+S->sred[g][2][2]+S->sred[g][3][2]) * (1.f/128.f);

    // ---- w1: chunks 0..4 ----
    u64 acc01 = 0, acc23 = 0;
    #pragma unroll
    for (int c = 0; c < 2; c++){
      WAITC();
      const float* B = S->buf[stC];
      const int rb = sl4 * 16;
      #pragma unroll
      for (int r = 0; r < 16; r++){
        u64 wp = pack2(B[(rb+r)*128 + jjm]);
        ulonglong2 xp = *(const ulonglong2*)&S->sciT[c*64 + rb + r][0];
        fma2(acc01, xp.x, wp); fma2(acc23, xp.y, wp);
      }
      ADVC();
    }
    __syncthreads(); PRODUCE(2);
    #pragma unroll
    for (int c = 2; c < 4; c++){
      WAITC();
      const float* B = S->buf[stC];
      const int rb = sl4 * 16;
      #pragma unroll
      for (int r = 0; r < 16; r++){
        u64 wp = pack2(B[(rb+r)*128 + jjm]);
        ulonglong2 xp = *(const ulonglong2*)&S->sciT[c*64 + rb + r][0];
        fma2(acc01, xp.x, wp); fma2(acc23, xp.y, wp);
      }
      ADVC();
    }
    __syncthreads(); PRODUCE(2);
    {
      WAITC();
      const float* B = S->buf[stC];
      u64 wp = pack2(B[sl4*128 + jjm]);
      ulonglong2 xp = *(const ulonglong2*)&S->sciT[256 + sl4][0];
      fma2(acc01, xp.x, wp); fma2(acc23, xp.y, wp);
      ADVC();
    }
    {
      float2 p = unpack2(acc01), q = unpack2(acc23);
      S->sbuf[sl4][0][jjm] = p.x; S->sbuf[sl4][1][jjm] = p.y;
      S->sbuf[sl4][2][jjm] = q.x; S->sbuf[sl4][3][jjm] = q.y;
    }
    __syncthreads(); PRODUCE(1);
    {
      float s = b1[ht] + S->sbuf[0][g][ht]+S->sbuf[1][g][ht]+S->sbuf[2][g][ht]+S->sbuf[3][g][ht];
      S->sh1T[ht][g] = tanhf(s);
    }
    __syncthreads();

    // ---- w2: chunks 5,6 ----
    acc01 = 0; acc23 = 0;
    #pragma unroll
    for (int c = 0; c < 2; c++){
      WAITC();
      const float* B = S->buf[stC];
      const int rb = sl4 * 16;
      #pragma unroll
      for (int r = 0; r < 16; r++){
        u64 wp = pack2(B[(rb+r)*128 + jjm]);
        ulonglong2 xp = *(const ulonglong2*)&S->sh1T[c*64 + rb + r][0];
        fma2(acc01, xp.x, wp); fma2(acc23, xp.y, wp);
      }
      ADVC();
    }
    {
      float2 p = unpack2(acc01), q = unpack2(acc23);
      S->sbuf[sl4][0][jjm] = p.x; S->sbuf[sl4][1][jjm] = p.y;
      S->sbuf[sl4][2][jjm] = q.x; S->sbuf[sl4][3][jjm] = q.y;
    }
    __syncthreads(); PRODUCE(2);
    {
      float s = b2[ht] + S->sbuf[0][g][ht]+S->sbuf[1][g][ht]+S->sbuf[2][g][ht]+S->sbuf[3][g][ht];
      S->sct2[ht][g] = tanhf(s);
    }
    __syncthreads();

    // ---- att: chunks 7,8 ----
    acc01 = 0; acc23 = 0;
    #pragma unroll
    for (int c = 0; c < 2; c++){
      WAITC();
      const float* B = S->buf[stC];
      const int rb = sl4 * 16;
      #pragma unroll
      for (int r = 0; r < 16; r++){
        u64 wp = pack2(B[(rb+r)*128 + jjm]);
        ulonglong2 xp = *(const ulonglong2*)&S->sct2[c*64 + rb + r][0];
        fma2(acc01, xp.x, wp); fma2(acc23, xp.y, wp);
      }
      ADVC();
    }
    {
      float2 p = unpack2(acc01), q = unpack2(acc23);
      S->sbuf[sl4][0][jjm] = p.x; S->sbuf[sl4][1][jjm] = p.y;
      S->sbuf[sl4][2][jjm] = q.x; S->sbuf[sl4][3][jjm] = q.y;
    }
    if (tid < 256){
      int w = tid >> 5; int g2 = w & 3; int rel = w >> 2;
      const float* vw = rel ? relax_w : nov_w;
      float s = 0.f;
      #pragma unroll
      for (int k = 0; k < 4; k++){ int i = lane + k*32; s += S->sct2[i][g2] * vw[i]; }
      s = rsum32(s);
      if (lane == 0){
        float r = sigm(s + (rel ? relax_b[0] : nov_b[0])) * S->sval[g2];
        if (rel) S->srl[g2] = r; else S->snv[g2] = r;
      }
    }
    __syncthreads(); PRODUCE(2);
    {
      float s = att_b[ht] + S->sbuf[0][g][ht]+S->sbuf[1][g][ht]+S->sbuf[2][g][ht]+S->sbuf[3][g][ht];
      S->satt[g][ht] = s;
    }
    __syncthreads();

    // ---- small heads: chunk 9 ----
    {
      WAITC();
      const float* B = S->buf[stC] + shd*2048;
      float4 a4 = make_float4(0.f,0.f,0.f,0.f);
      const int i0 = shs * 16;
      #pragma unroll
      for (int i = i0; i < i0 + 16; i++){
        float w = B[i*16 + shc];
        float4 x = *(const float4*)&S->sct2[i][0];
        a4.x += x.x*w; a4.y += x.y*w; a4.z += x.z*w; a4.w += x.w*w;
      }
      ((float4*)S->sbuf)[(shd*16 + shc)*8 + shs] = a4;
      ADVC();
    }
    __syncthreads(); PRODUCE(1);

    if (ht < 32){
      const bool ok = lane < 16;
      float graw = -3.4e38f, araw = -3.4e38f, csr = 0.f, mdr = 0.f;
      if (ok){
        const float* spf = (const float*)S->sbuf;
        float r0=0.f, r1=0.f, r2=0.f, r3=0.f;
        #pragma unroll
        for (int s2 = 0; s2 < 8; s2++){
          r0 += spf[(((0*16+lane)*8)+s2)*4 + g];
          r1 += spf[(((1*16+lane)*8)+s2)*4 + g];
          r2 += spf[(((2*16+lane)*8)+s2)*4 + g];
          r3 += spf[(((3*16+lane)*8)+s2)*4 + g];
        }
        graw = r0 + gate_b[lane]; araw = r1 + assign_b[lane];
        csr  = r2 + cs_b[lane];   mdr  = r3 + md_b[lane];
      }
      float mx = rmax16(araw);
      float ex = ok ? expf(araw - mx) : 0.f;
      float sm = rsum16(ex);
      if (ok){
        float assign = ex / sm;
        float gate = sigm(graw) * S->sval[g];
        float ss = gate * assign;
        S->sgs[g][lane] = ss;
        float cs = splus(csr) + EPSF;
        float md = tanhf(mdr);
        float sp = S->ssp[g][lane]; sp += ss*(cs - sp); S->ssp[g][lane] = sp;
        float m  = S->smaM[g][lane]; m += ss*md;        S->smaM[g][lane] = m;
      }
    }

    // ---- cc: chunks 10..41 ----
    u64 A0[2] = {0,0}, A1[2] = {0,0}, A2[2] = {0,0}, A3[2] = {0,0};
    #pragma unroll 1
    for (int grp = 0; grp < 8; grp++){
      #pragma unroll
      for (int q = 0; q < 4; q++){
        WAITC();
        const ulonglong2* Wb = (const ulonglong2*)S->buf[stC];
        const int i0 = grp*16 + q*4;
        #pragma unroll
        for (int i2 = 0; i2 < 4; i2++){
          ulonglong2 wv = Wb[i2*512 + tid];
          float4 ct = *(const float4*)&S->sct2[i0 + i2][0];
          u64 p0 = pack2(ct.x), p1 = pack2(ct.y), p2 = pack2(ct.z), p3 = pack2(ct.w);
          fma2(A0[0], p0, wv.x); fma2(A0[1], p0, wv.y);
          fma2(A1[0], p1, wv.x); fma2(A1[1], p1, wv.y);
          fma2(A2[0], p2, wv.x); fma2(A2[1], p2, wv.y);
          fma2(A3[0], p3, wv.x); fma2(A3[1], p3, wv.y);
        }
        ADVC();
      }
      __syncthreads(); PRODUCE(4);
    }

    // ---- center update ----
    {
      const int ccC = tid >> 5, ccH = tid & 31;
      float4 bv = *(const float4*)&cc_b[ccC*128 + ccH*4];
      u64* Ap[4] = {A0, A1, A2, A3};
      #pragma unroll
      for (int gg = 0; gg < 4; gg++){
        float2 l  = unpack2(Ap[gg][0]);
        float2 hh = unpack2(Ap[gg][1]);
        float4 cand = make_float4(l.x+bv.x, l.y+bv.y, hh.x+bv.z, hh.y+bv.w);
        float ssv = S->sgs[gg][ccC];
        float nv  = 0.1f * S->snv[gg];
        float4 at = *(const float4*)&S->satt[gg][ccH*4];
        float4 v  = *(float4*)&S->sc[gg][ccC][ccH*4];
        v.x += ssv*(cand.x - v.x); v.x += nv*(at.x - v.x);
        v.y += ssv*(cand.y - v.y); v.y += nv*(at.y - v.y);
        v.z += ssv*(cand.z - v.z); v.z += nv*(at.z - v.z);
        v.w += ssv*(cand.w - v.w); v.w += nv*(at.w - v.w);
        *(float4*)&S->sc[gg][ccC][ccH*4] = v;
      }
    }
    __syncthreads(); // S9

    {
      #pragma unroll
      for (int pp = 0; pp < 2; pp++){
        int p = ht + pp*128;
        int ii = p >> 4, jj = p & 15;
        const float4* Aa = (const float4*)S->sc[g][ii];
        const float4* Bv = (const float4*)S->sc[g][jj];
        float d0=0.f, d1=0.f, d2s=0.f, d3=0.f;
        #pragma unroll 8
        for (int k = 0; k < 32; k++){
          float4 a4 = Aa[k], b4 = Bv[k];
          d0 += a4.x*b4.x; d1 += a4.y*b4.y; d2s += a4.z*b4.z; d3 += a4.w*b4.w;
        }
        float dot = (d0+d1) + (d2s+d3);
        S->smix[g][ii][jj] = dot;
        if (ii == jj) S->ssq[g][ii] = dot;
      }
    }
    __syncthreads(); // S10
    {
      #pragma unroll
      for (int pass = 0; pass < 2; pass++){
        int row = pass*8 + wg*2 + (lane >> 4);
        int jj  = lane & 15;
        float Gij = S->smix[g][row][jj];
        float d2v = fmaxf(S->ssq[g][row] + S->ssq[g][jj] - 2.f*Gij, 0.f);
        float comp = -d2v / (S->ssp[g][row] + S->ssp[g][jj] + EPSF) + S->smaM[g][jj];
        float mx = rmax16(comp);
        float ex = expf(comp - mx);
        float sm = rsum16(ex);
        float mix = ex / sm;
        S->smix[g][row][jj] = mix;
        float msp = rsum16(mix * S->ssp[g][jj]);
        float mms = rsum16(mix * S->smaM[g][jj]);
        if ((lane & 15) == 0){ S->sms[g][row] = msp; S->smm[g][row] = mms; }
      }
    }
    __syncthreads(); // S11
    {
      float rl = S->srl[g];
      float cr[16];
      #pragma unroll
      for (int c = 0; c < 16; c++) cr[c] = S->sc[g][c][ht];
      #pragma unroll
      for (int i = 0; i < 16; i++){
        const float4* mr = (const float4*)S->smix[g][i];
        float4 m0 = mr[0], m1 = mr[1], m2v = mr[2], m3 = mr[3];
        float mc = m0.x*cr[0]+m0.y*cr[1]+m0.z*cr[2]+m0.w*cr[3]
                 + m1.x*cr[4]+m1.y*cr[5]+m1.z*cr[6]+m1.w*cr[7]
                 + m2v.x*cr[8]+m2v.y*cr[9]+m2v.z*cr[10]+m2v.w*cr[11]
                 + m3.x*cr[12]+m3.y*cr[13]+m3.z*cr[14]+m3.w*cr[15];
        S->sc[g][i][ht] = (1.f-rl)*cr[i] + rl*mc;
      }
      if (ht < 32){
        const bool ok = lane < 16;
        float rl2 = S->srl[g];
        float sp = ok ? S->ssp[g][lane] : 1.f;
        float m  = ok ? S->smaM[g][lane] : 0.f;
        float sp2 = (1.f-rl2)*sp + rl2*(ok ? S->sms[g][lane] : 0.f);
        float m2  = (1.f-rl2)*m  + rl2*(ok ? S->smm[g][lane] : 0.f);
        float score = ok ? m2 + logf(1.f/(sp2+EPSF)+EPSF) : -3.4e38f;
        float mx = rmax16(score);
        float ex = ok ? expf(score - mx) : 0.f;
        float sm = rsum16(ex);
        float ca = ex / sm;
        if (ok){ S->ssp[g][lane] = sp2*(1.f - 0.05f*ca*S->sval[g]) + EPSF; S->smaM[g][lane] = m2; }
      }
    }
    __syncthreads(); // S12
  }

  // ---- epilogue ----
  const int isl = ht >> 5;
  const int j4  = ht & 31;
  if (ht < 32){
    const bool ok = lane < 16;
    float sp = ok ? S->ssp[g][lane] : 0.f;
    float m  = ok ? S->smaM[g][lane] : 0.f;
    float score = ok ? m + logf(1.f/(sp+EPSF)+EPSF) : -3.4e38f;
    float mx = rmax16(score);
    float ex = ok ? expf(score - mx) : 0.f;
    float sm = rsum16(ex);
    float a  = ex / sm;
    if (ok) S->sal[g][lane] = a;
    float u   = rsum16(ok ? a*sp : 0.f);
    float ent = rsum16(ok ? -a*logf(fmaxf(a,1e-8f)) : 0.f);
    float mm2 = rmax16(ok ? m : -3.4e38f);
    float en  = mm2 + logf(rsum16(ok ? expf(m - mm2) : 0.f));
    float bv = ok ? a : -3.4e38f;
    int   bi = ok ? lane : 99;
    #pragma unroll
    for (int o = 8; o; o >>= 1){
      float ov = __shfl_xor_sync(0xffffffffu, bv, o);
      int   oi = __shfl_xor_sync(0xffffffffu, bi, o);
      if (ov > bv || (ov == bv && oi < bi)){ bv = ov; bi = oi; }
    }
    if (lane == 0){
      S->sciT[256][g] = u; S->sciT[258][g] = en; S->sciT[259][g] = ent; S->sidx[g] = bi;
    }
  }
  __syncthreads();
  {
    float core = 0.f;
    #pragma unroll
    for (int c = 0; c < 16; c++) core += S->sal[g][c] * S->sc[g][c][ht];
    float dv = 0.f;
    #pragma unroll
    for (int c = 0; c < 16; c++){ float dd = S->sc[g][c][ht] - core; dv += S->sal[g][c]*dd*dd; }
    dv = rsum32(dv);
    if (lane == 0) S->sred[g][wg][2] = dv;
    float strong = S->sc[g][S->sidx[g]][ht];
    S->sciT[ht][g] = core;
    S->sciT[128+ht][g] = strong;
  }
  __syncthreads();
  if (ht == 0)
    S->sciT[257][g] = (S->sred[g][0][2]+S->sred[g][1][2]+S->sred[g][2][2]+S->sred[g][3][2]) * (1.f/128.f);
  __syncthreads();
  {
    u64 a0 = 0, a1 = 0;
    const int lo = isl * 65;
    #pragma unroll 4
    for (int i = lo; i < lo + 65; i++){
      u64 xp = pack2(S->sciT[i][g]);
      ulonglong2 w = *(const ulonglong2*)&cw1[i*128 + j4*4];
      fma2(a0, xp, w.x); fma2(a1, xp, w.y);
    }
    float2 l = unpack2(a0), h2 = unpack2(a1);
    *(float4*)&S->sbuf[isl][g][j4*4] = make_float4(l.x, l.y, h2.x, h2.y);
  }
  __syncthreads();
  {
    float s = cb1[ht] + S->sbuf[0][g][ht]+S->sbuf[1][g][ht]+S->sbuf[2][g][ht]+S->sbuf[3][g][ht];
    S->sh1T[ht][g] = 0.5f * s * (1.f + erff(s * 0.70710678118654752440f));
  }
  __syncthreads();
  if (ht < 8){
    float s = cb2[ht];
    #pragma unroll 4
    for (int i = 0; i < 128; i++) s += S->sh1T[i][g] * cw2[i*8 + ht];
    out[b*8 + ht] = s;
  }
}

extern "C" void kernel_launch(void* const* d_in, const int* in_sizes, int n_in,
                              void* d_out, int out_size){
  (void)in_sizes; (void)n_in; (void)out_size;
  cudaFuncSetAttribute(cfrm_kernel, cudaFuncAttributeMaxDynamicSharedMemorySize, (int)sizeof(Smem));
  cfrm_kernel<<<32, 512, sizeof(Smem)>>>(
    (const int*)  d_in[0],  (const float*)d_in[1],  (const float*)d_in[2],  (const float*)d_in[3],
    (const float*)d_in[4],  (const float*)d_in[5],  (const float*)d_in[6],  (const float*)d_in[7],
    (const float*)d_in[8],  (const float*)d_in[9],  (const float*)d_in[10], (const float*)d_in[11],
    (const float*)d_in[12], (const float*)d_in[13], (const float*)d_in[14], (const float*)d_in[15],
    (const float*)d_in[16], (const float*)d_in[17], (const float*)d_in[18], (const float*)d_in[19],
    (const float*)d_in[20], (const float*)d_in[21], (const float*)d_in[22], (const float*)d_in[23],
    (const float*)d_in[24], (const float*)d_in[25], (const float*)d_in[26], (const float*)d_in[27],
    (float*)d_out);
}

// round 8
// speedup vs baseline: 1.4854x; 1.4854x over previous
#include <cuda_runtime.h>
#include <math.h>

#define EPSF 1e-4f
typedef unsigned long long u64;

__device__ __forceinline__ u64 pack2(float x){
  u64 r; unsigned xi = __float_as_uint(x);
  asm("mov.b64 %0, {%1, %1};" : "=l"(r) : "r"(xi));
  return r;
}
__device__ __forceinline__ void fma2(u64 &acc, u64 a, u64 b){
  asm("fma.rn.f32x2 %0, %1, %2, %0;" : "+l"(acc) : "l"(a), "l"(b));
}
__device__ __forceinline__ float2 unpack2(u64 v){
  unsigned lo, hi;
  asm("mov.b64 {%0, %1}, %2;" : "=r"(lo), "=r"(hi) : "l"(v));
  return make_float2(__uint_as_float(lo), __uint_as_float(hi));
}
__device__ __forceinline__ float rsum32(float v){
  #pragma unroll
  for (int o=16;o;o>>=1) v += __shfl_xor_sync(0xffffffffu, v, o);
  return v;
}
__device__ __forceinline__ float rsum16(float v){
  #pragma unroll
  for (int o=8;o;o>>=1) v += __shfl_xor_sync(0xffffffffu, v, o);
  return v;
}
__device__ __forceinline__ float rmax16(float v){
  #pragma unroll
  for (int o=8;o;o>>=1) v = fmaxf(v, __shfl_xor_sync(0xffffffffu, v, o));
  return v;
}
__device__ __forceinline__ float sigm(float x){ return 1.f/(1.f+expf(-x)); }
__device__ __forceinline__ float splus(float x){ return fmaxf(x,0.f)+log1pf(expf(-fabsf(x))); }

struct Smem {
  float sciT[260][4];
  float sh1T[128][4];
  float sct2[128][4];
  float sc[4][16][132];
  float smix[4][16][16];
  float satt[4][128];
  float sbuf[16][4][128];     // 16-slice matvec partials (32KB)
  float ssp[4][16], smaM[4][16], sal[4][16], sgs[4][16];
  float ssq[4][16], sms[4][16], smm[4][16];
  float sraw[4][4][16];
  float sred[4][4][3];
  float snv[4], srl[4], sval[4];
  int   sidx[4];
};

__global__ void __launch_bounds__(512,1) cfrm_kernel(
   const int* __restrict__ tokens, const float* __restrict__ emb,
   const float* __restrict__ ln_g, const float* __restrict__ ln_b,
   const float* __restrict__ w1, const float* __restrict__ b1,
   const float* __restrict__ w2, const float* __restrict__ b2,
   const float* __restrict__ gate_w, const float* __restrict__ gate_b,
   const float* __restrict__ assign_w, const float* __restrict__ assign_b,
   const float* __restrict__ nov_w, const float* __restrict__ nov_b,
   const float* __restrict__ relax_w, const float* __restrict__ relax_b,
   const float* __restrict__ cc_w, const float* __restrict__ cc_b,
   const float* __restrict__ cs_w, const float* __restrict__ cs_b,
   const float* __restrict__ md_w, const float* __restrict__ md_b,
   const float* __restrict__ att_w, const float* __restrict__ att_b,
   const float* __restrict__ cw1, const float* __restrict__ cb1,
   const float* __restrict__ cw2, const float* __restrict__ cb2,
   float* __restrict__ out)
{
  extern __shared__ __align__(128) char smem_raw[];
  Smem* S = (Smem*)smem_raw;

  const int tid  = threadIdx.x;
  const int g    = tid >> 7;
  const int ht   = tid & 127;
  const int lane = tid & 31;
  const int wg   = (tid >> 5) & 3;
  const int b    = blockIdx.x * 4 + g;

  const int j4  = tid & 31;     // float4 output chunk for w1/w2/att
  const int isl = tid >> 5;     // reduction slice 0..15

  for (int i = tid; i < 4*16*132; i += 512) ((float*)S->sc)[i] = 0.f;
  if (tid < 64){ ((float*)S->ssp)[tid] = 1.f; ((float*)S->smaM)[tid] = 0.f; }
  __syncthreads();

  for (int t = 0; t < 512; t++){
    const int tok = tokens[b*512 + t];
    const float valid = (tok != 0) ? 1.f : 0.f;
    if (ht == 0) S->sval[g] = valid;
    const float e = emb[tok*128 + ht];
    {
      float ps = rsum32(e);
      float pq = rsum32(e*e);
      if (lane == 0){ S->sred[g][wg][0] = ps; S->sred[g][wg][1] = pq; }
    }
    if (ht < 32){
      const bool ok = lane < 16;
      float sp = ok ? S->ssp[g][lane] : 0.f;
      float m  = ok ? S->smaM[g][lane] : 0.f;
      float score = ok ? m + logf(1.f/(sp+EPSF)+EPSF) : -3.4e38f;
      float mx = rmax16(score);
      float ex = ok ? expf(score - mx) : 0.f;
      float sm = rsum16(ex);
      float a  = ex / sm;
      if (ok) S->sal[g][lane] = a;
      float u   = rsum16(ok ? a*sp : 0.f);
      float ent = rsum16(ok ? -a*logf(fmaxf(a,1e-8f)) : 0.f);
      float mm2 = rmax16(ok ? m : -3.4e38f);
      float en  = mm2 + logf(rsum16(ok ? expf(m - mm2) : 0.f));
      if (lane == 0){ S->sciT[256][g] = u; S->sciT[258][g] = en; S->sciT[259][g] = ent; }
    }
    __syncthreads(); // S1
    {
      float mu = (S->sred[g][0][0]+S->sred[g][1][0]+S->sred[g][2][0]+S->sred[g][3][0]) * (1.f/128.f);
      float mq = (S->sred[g][0][1]+S->sred[g][1][1]+S->sred[g][2][1]+S->sred[g][3][1]) * (1.f/128.f);
      float var = mq - mu*mu;
      float te = (e - mu) * rsqrtf(var + 1e-5f) * ln_g[ht] + ln_b[ht];
      S->sciT[ht][g] = te;
      float core = 0.f;
      #pragma unroll
      for (int c = 0; c < 16; c++) core += S->sal[g][c] * S->sc[g][c][ht];
      S->sciT[128+ht][g] = core;
      float dv = 0.f;
      #pragma unroll
      for (int c = 0; c < 16; c++){ float dd = S->sc[g][c][ht] - core; dv += S->sal[g][c]*dd*dd; }
      dv = rsum32(dv);
      if (lane == 0) S->sred[g][wg][2] = dv;
    }
    __syncthreads(); // S2a
    if (ht == 0)
      S->sciT[257][g] = (S->sred[g][0][2]+S->sred[g][1][2]+S->sred[g][2][2]+S->sred[g][3][2]) * (1.f/128.f);
    __syncthreads(); // S2b

    // ---- w1 [260,128]: 16 slices x 32 float4 chunks, LDG.128 + FFMA2 ----
    {
      u64 aA[4] = {0,0,0,0}, aB[4] = {0,0,0,0};
      const int lo = isl * 16;
      #pragma unroll 8
      for (int i = lo; i < lo + 16; i++){
        ulonglong2 w = *(const ulonglong2*)&w1[i*128 + j4*4];
        float4 x = *(const float4*)&S->sciT[i][0];
        u64 p0=pack2(x.x), p1=pack2(x.y), p2=pack2(x.z), p3=pack2(x.w);
        fma2(aA[0], p0, w.x); fma2(aB[0], p0, w.y);
        fma2(aA[1], p1, w.x); fma2(aB[1], p1, w.y);
        fma2(aA[2], p2, w.x); fma2(aB[2], p2, w.y);
        fma2(aA[3], p3, w.x); fma2(aB[3], p3, w.y);
      }
      if (isl < 4){
        const int i = 256 + isl;
        ulonglong2 w = *(const ulonglong2*)&w1[i*128 + j4*4];
        float4 x = *(const float4*)&S->sciT[i][0];
        u64 p0=pack2(x.x), p1=pack2(x.y), p2=pack2(x.z), p3=pack2(x.w);
        fma2(aA[0], p0, w.x); fma2(aB[0], p0, w.y);
        fma2(aA[1], p1, w.x); fma2(aB[1], p1, w.y);
        fma2(aA[2], p2, w.x); fma2(aB[2], p2, w.y);
        fma2(aA[3], p3, w.x); fma2(aB[3], p3, w.y);
      }
      #pragma unroll
      for (int b2 = 0; b2 < 4; b2++){
        float2 l = unpack2(aA[b2]), h2 = unpack2(aB[b2]);
        *(float4*)&S->sbuf[isl][b2][j4*4] = make_float4(l.x, l.y, h2.x, h2.y);
      }
    }
    __syncthreads(); // S3
    {
      float s = b1[ht];
      #pragma unroll
      for (int k = 0; k < 16; k++) s += S->sbuf[k][g][ht];
      S->sh1T[ht][g] = tanhf(s);
    }
    __syncthreads(); // S4

    // ---- w2 [128,128] ----
    {
      u64 aA[4] = {0,0,0,0}, aB[4] = {0,0,0,0};
      const int lo = isl * 8;
      #pragma unroll 8
      for (int i = lo; i < lo + 8; i++){
        ulonglong2 w = *(const ulonglong2*)&w2[i*128 + j4*4];
        float4 x = *(const float4*)&S->sh1T[i][0];
        u64 p0=pack2(x.x), p1=pack2(x.y), p2=pack2(x.z), p3=pack2(x.w);
        fma2(aA[0], p0, w.x); fma2(aB[0], p0, w.y);
        fma2(aA[1], p1, w.x); fma2(aB[1], p1, w.y);
        fma2(aA[2], p2, w.x); fma2(aB[2], p2, w.y);
        fma2(aA[3], p3, w.x); fma2(aB[3], p3, w.y);
      }
      #pragma unroll
      for (int b2 = 0; b2 < 4; b2++){
        float2 l = unpack2(aA[b2]), h2 = unpack2(aB[b2]);
        *(float4*)&S->sbuf[isl][b2][j4*4] = make_float4(l.x, l.y, h2.x, h2.y);
      }
    }
    __syncthreads(); // S5
    {
      float s = b2[ht];
      #pragma unroll
      for (int k = 0; k < 16; k++) s += S->sbuf[k][g][ht];
      S->sct2[ht][g] = tanhf(s);
    }
    __syncthreads(); // S6

    // ---- cc_w [128,2048]: one LDG.128 feeds 4 batches ----
    u64 A0[2] = {0,0}, A1[2] = {0,0}, A2[2] = {0,0}, A3[2] = {0,0};
    {
      const ulonglong2* W = (const ulonglong2*)cc_w;
      #pragma unroll 8
      for (int i = 0; i < 128; i++){
        ulonglong2 wv = W[i*512 + tid];
        float4 ct = *(const float4*)&S->sct2[i][0];
        u64 p0 = pack2(ct.x), p1 = pack2(ct.y), p2 = pack2(ct.z), p3 = pack2(ct.w);
        fma2(A0[0], p0, wv.x); fma2(A0[1], p0, wv.y);
        fma2(A1[0], p1, wv.x); fma2(A1[1], p1, wv.y);
        fma2(A2[0], p2, wv.x); fma2(A2[1], p2, wv.y);
        fma2(A3[0], p3, wv.x); fma2(A3[1], p3, wv.y);
      }
    }

    // ---- att_w [128,128] ----
    {
      u64 aA[4] = {0,0,0,0}, aB[4] = {0,0,0,0};
      const int lo = isl * 8;
      #pragma unroll 8
      for (int i = lo; i < lo + 8; i++){
        ulonglong2 w = *(const ulonglong2*)&att_w[i*128 + j4*4];
        float4 x = *(const float4*)&S->sct2[i][0];
        u64 p0=pack2(x.x), p1=pack2(x.y), p2=pack2(x.z), p3=pack2(x.w);
        fma2(aA[0], p0, w.x); fma2(aB[0], p0, w.y);
        fma2(aA[1], p1, w.x); fma2(aB[1], p1, w.y);
        fma2(aA[2], p2, w.x); fma2(aB[2], p2, w.y);
        fma2(aA[3], p3, w.x); fma2(aB[3], p3, w.y);
      }
      #pragma unroll
      for (int b2 = 0; b2 < 4; b2++){
        float2 l = unpack2(aA[b2]), h2 = unpack2(aB[b2]);
        *(float4*)&S->sbuf[isl][b2][j4*4] = make_float4(l.x, l.y, h2.x, h2.y);
      }
    }

    // ---- small heads + nov/relax (overlapped with cc/att region) ----
    if (ht < 64){
      const int head = ht >> 4;
      const int c = ht & 15;
      const float* W  = (head==0)? gate_w : (head==1)? assign_w : (head==2)? cs_w : md_w;
      const float* Bp = (head==0)? gate_b : (head==1)? assign_b : (head==2)? cs_b : md_b;
      float s = Bp[c];
      #pragma unroll 8
      for (int i = 0; i < 128; i++) s += S->sct2[i][g] * W[i*16 + c];
      S->sraw[g][head][c] = s;
    } else if (ht < 96){
      float s = 0.f;
      #pragma unroll
      for (int k = 0; k < 4; k++){ int i = (ht-64) + k*32; s += S->sct2[i][g] * nov_w[i]; }
      s = rsum32(s);
      if (lane == 0) S->snv[g] = sigm(s + nov_b[0]) * S->sval[g];
    } else {
      float s = 0.f;
      #pragma unroll
      for (int k = 0; k < 4; k++){ int i = (ht-96) + k*32; s += S->sct2[i][g] * relax_w[i]; }
      s = rsum32(s);
      if (lane == 0) S->srl[g] = sigm(s + relax_b[0]) * S->sval[g];
    }
    __syncthreads(); // S7
    {
      float s = att_b[ht];
      #pragma unroll
      for (int k = 0; k < 16; k++) s += S->sbuf[k][g][ht];
      S->satt[g][ht] = s;
    }
    if (ht < 32){
      const bool ok = lane < 16;
      float graw = ok ? S->sraw[g][0][lane] : 0.f;
      float araw = ok ? S->sraw[g][1][lane] : -3.4e38f;
      float mx = rmax16(araw);
      float ex = ok ? expf(araw - mx) : 0.f;
      float sm = rsum16(ex);
      if (ok){
        float assign = ex / sm;
        float gate = sigm(graw) * S->sval[g];
        float ss = gate * assign;
        S->sgs[g][lane] = ss;
        float cs = splus(S->sraw[g][2][lane]) + EPSF;
        float md = tanhf(S->sraw[g][3][lane]);
        float sp = S->ssp[g][lane]; sp += ss*(cs - sp); S->ssp[g][lane] = sp;
        float m  = S->smaM[g][lane]; m += ss*md;        S->smaM[g][lane] = m;
      }
    }
    __syncthreads(); // S8

    // ---- center update ----
    {
      const int ccC = tid >> 5, ccH = tid & 31;
      float4 bv = *(const float4*)&cc_b[ccC*128 + ccH*4];
      u64* Ap[4] = {A0, A1, A2, A3};
      #pragma unroll
      for (int gg = 0; gg < 4; gg++){
        float2 l  = unpack2(Ap[gg][0]);
        float2 hh = unpack2(Ap[gg][1]);
        float4 cand = make_float4(l.x+bv.x, l.y+bv.y, hh.x+bv.z, hh.y+bv.w);
        float ssv = S->sgs[gg][ccC];
        float nv  = 0.1f * S->snv[gg];
        float4 at = *(const float4*)&S->satt[gg][ccH*4];
        float4 v  = *(float4*)&S->sc[gg][ccC][ccH*4];
        v.x += ssv*(cand.x - v.x); v.x += nv*(at.x - v.x);
        v.y += ssv*(cand.y - v.y); v.y += nv*(at.y - v.y);
        v.z += ssv*(cand.z - v.z); v.z += nv*(at.z - v.z);
        v.w += ssv*(cand.w - v.w); v.w += nv*(at.w - v.w);
        *(float4*)&S->sc[gg][ccC][ccH*4] = v;
      }
    }
    __syncthreads(); // S9

    // ---- Gram ----
    {
      #pragma unroll
      for (int pp = 0; pp < 2; pp++){
        int p = ht + pp*128;
        int ii = p >> 4, jj = p & 15;
        const float4* Aa = (const float4*)S->sc[g][ii];
        const float4* Bv = (const float4*)S->sc[g][jj];
        float d0=0.f, d1=0.f, d2s=0.f, d3=0.f;
        #pragma unroll 8
        for (int k = 0; k < 32; k++){
          float4 a4 = Aa[k], b4 = Bv[k];
          d0 += a4.x*b4.x; d1 += a4.y*b4.y; d2s += a4.z*b4.z; d3 += a4.w*b4.w;
        }
        float dot = (d0+d1) + (d2s+d3);
        S->smix[g][ii][jj] = dot;
        if (ii == jj) S->ssq[g][ii] = dot;
      }
    }
    __syncthreads(); // S10
    {
      #pragma unroll
      for (int pass = 0; pass < 2; pass++){
        int row = pass*8 + wg*2 + (lane >> 4);
        int jj  = lane & 15;
        float Gij = S->smix[g][row][jj];
        float d2v = fmaxf(S->ssq[g][row] + S->ssq[g][jj] - 2.f*Gij, 0.f);
        float comp = -d2v / (S->ssp[g][row] + S->ssp[g][jj] + EPSF) + S->smaM[g][jj];
        float mx = rmax16(comp);
        float ex = expf(comp - mx);
        float sm = rsum16(ex);
        float mix = ex / sm;
        S->smix[g][row][jj] = mix;
        float msp = rsum16(mix * S->ssp[g][jj]);
        float mms = rsum16(mix * S->smaM[g][jj]);
        if ((lane & 15) == 0){ S->sms[g][row] = msp; S->smm[g][row] = mms; }
      }
    }
    __syncthreads(); // S11
    {
      float rl = S->srl[g];
      float cr[16];
      #pragma unroll
      for (int c = 0; c < 16; c++) cr[c] = S->sc[g][c][ht];
      #pragma unroll
      for (int i = 0; i < 16; i++){
        const float4* mr = (const float4*)S->smix[g][i];
        float4 m0 = mr[0], m1 = mr[1], m2v = mr[2], m3 = mr[3];
        float mc = m0.x*cr[0]+m0.y*cr[1]+m0.z*cr[2]+m0.w*cr[3]
                 + m1.x*cr[4]+m1.y*cr[5]+m1.z*cr[6]+m1.w*cr[7]
                 + m2v.x*cr[8]+m2v.y*cr[9]+m2v.z*cr[10]+m2v.w*cr[11]
                 + m3.x*cr[12]+m3.y*cr[13]+m3.z*cr[14]+m3.w*cr[15];
        S->sc[g][i][ht] = (1.f-rl)*cr[i] + rl*mc;
      }
      if (ht < 32){
        const bool ok = lane < 16;
        float rl2 = S->srl[g];
        float sp = ok ? S->ssp[g][lane] : 1.f;
        float m  = ok ? S->smaM[g][lane] : 0.f;
        float sp2 = (1.f-rl2)*sp + rl2*(ok ? S->sms[g][lane] : 0.f);
        float m2  = (1.f-rl2)*m  + rl2*(ok ? S->smm[g][lane] : 0.f);
        float score = ok ? m2 + logf(1.f/(sp2+EPSF)+EPSF) : -3.4e38f;
        float mx = rmax16(score);
        float ex = ok ? expf(score - mx) : 0.f;
        float sm = rsum16(ex);
        float ca = ex / sm;
        if (ok){ S->ssp[g][lane] = sp2*(1.f - 0.05f*ca*S->sval[g]) + EPSF; S->smaM[g][lane] = m2; }
      }
    }
    __syncthreads(); // S12
  }

  // ---- epilogue ----
  if (ht < 32){
    const bool ok = lane < 16;
    float sp = ok ? S->ssp[g][lane] : 0.f;
    float m  = ok ? S->smaM[g][lane] : 0.f;
    float score = ok ? m + logf(1.f/(sp+EPSF)+EPSF) : -3.4e38f;
    float mx = rmax16(score);
    float ex = ok ? expf(score - mx) : 0.f;
    float sm = rsum16(ex);
    float a  = ex / sm;
    if (ok) S->sal[g][lane] = a;
    float u   = rsum16(ok ? a*sp : 0.f);
    float ent = rsum16(ok ? -a*logf(fmaxf(a,1e-8f)) : 0.f);
    float mm2 = rmax16(ok ? m : -3.4e38f);
    float en  = mm2 + logf(rsum16(ok ? expf(m - mm2) : 0.f));
    float bv = ok ? a : -3.4e38f;
    int   bi = ok ? lane : 99;
    #pragma unroll
    for (int o = 8; o; o >>= 1){
      float ov = __shfl_xor_sync(0xffffffffu, bv, o);
      int   oi = __shfl_xor_sync(0xffffffffu, bi, o);
      if (ov > bv || (ov == bv && oi < bi)){ bv = ov; bi = oi; }
    }
    if (lane == 0){
      S->sciT[256][g] = u; S->sciT[258][g] = en; S->sciT[259][g] = ent; S->sidx[g] = bi;
    }
  }
  __syncthreads();
  {
    float core = 0.f;
    #pragma unroll
    for (int c = 0; c < 16; c++) core += S->sal[g][c] * S->sc[g][c][ht];
    float dv = 0.f;
    #pragma unroll
    for (int c = 0; c < 16; c++){ float dd = S->sc[g][c][ht] - core; dv += S->sal[g][c]*dd*dd; }
    dv = rsum32(dv);
    if (lane == 0) S->sred[g][wg][2] = dv;
    float strong = S->sc[g][S->sidx[g]][ht];
    S->sciT[ht][g] = core;
    S->sciT[128+ht][g] = strong;
  }
  __syncthreads();
  if (ht == 0)
    S->sciT[257][g] = (S->sred[g][0][2]+S->sred[g][1][2]+S->sred[g][2][2]+S->sred[g][3][2]) * (1.f/128.f);
  __syncthreads();
  {
    // cls_w1 [260,128]: same 16-slice decomposition
    u64 aA[4] = {0,0,0,0}, aB[4] = {0,0,0,0};
    const int lo = isl * 16;
    #pragma unroll 8
    for (int i = lo; i < lo + 16; i++){
      ulonglong2 w = *(const ulonglong2*)&cw1[i*128 + j4*4];
      float4 x = *(const float4*)&S->sciT[i][0];
      u64 p0=pack2(x.x), p1=pack2(x.y), p2=pack2(x.z), p3=pack2(x.w);
      fma2(aA[0], p0, w.x); fma2(aB[0], p0, w.y);
      fma2(aA[1], p1, w.x); fma2(aB[1], p1, w.y);
      fma2(aA[2], p2, w.x); fma2(aB[2], p2, w.y);
      fma2(aA[3], p3, w.x); fma2(aB[3], p3, w.y);
    }
    if (isl < 4){
      const int i = 256 + isl;
      ulonglong2 w = *(const ulonglong2*)&cw1[i*128 + j4*4];
      float4 x = *(const float4*)&S->sciT[i][0];
      u64 p0=pack2(x.x), p1=pack2(x.y), p2=pack2(x.z), p3=pack2(x.w);
      fma2(aA[0], p0, w.x); fma2(aB[0], p0, w.y);
      fma2(aA[1], p1, w.x); fma2(aB[1], p1, w.y);
      fma2(aA[2], p2, w.x); fma2(aB[2], p2, w.y);
      fma2(aA[3], p3, w.x); fma2(aB[3], p3, w.y);
    }
    #pragma unroll
    for (int b2 = 0; b2 < 4; b2++){
      float2 l = unpack2(aA[b2]), h2 = unpack2(aB[b2]);
      *(float4*)&S->sbuf[isl][b2][j4*4] = make_float4(l.x, l.y, h2.x, h2.y);
    }
  }
  __syncthreads();
  {
    float s = cb1[ht];
    #pragma unroll
    for (int k = 0; k < 16; k++) s += S->sbuf[k][g][ht];
    S->sh1T[ht][g] = 0.5f * s * (1.f + erff(s * 0.70710678118654752440f));
  }
  __syncthreads();
  if (ht < 8){
    float s = cb2[ht];
    #pragma unroll 4
    for (int i = 0; i < 128; i++) s += S->sh1T[i][g] * cw2[i*8 + ht];
    out[b*8 + ht] = s;
  }
}

extern "C" void kernel_launch(void* const* d_in, const int* in_sizes, int n_in,
                              void* d_out, int out_size){
  (void)in_sizes; (void)n_in; (void)out_size;
  cudaFuncSetAttribute(cfrm_kernel, cudaFuncAttributeMaxDynamicSharedMemorySize, (int)sizeof(Smem));
  cfrm_kernel<<<32, 512, sizeof(Smem)>>>(
    (const int*)  d_in[0],  (const float*)d_in[1],  (const float*)d_in[2],  (const float*)d_in[3],
    (const float*)d_in[4],  (const float*)d_in[5],  (const float*)d_in[6],  (const float*)d_in[7],
    (const float*)d_in[8],  (const float*)d_in[9],  (const float*)d_in[10], (const float*)d_in[11],
    (const float*)d_in[12], (const float*)d_in[13], (const float*)d_in[14], (const float*)d_in[15],
    (const float*)d_in[16], (const float*)d_in[17], (const float*)d_in[18], (const float*)d_in[19],
    (const float*)d_in[20], (const float*)d_in[21], (const float*)d_in[22], (const float*)d_in[23],
    (const float*)d_in[24], (const float*)d_in[25], (const float*)d_in[26], (const float*)d_in[27],
    (float*)d_out);
}